// round 4
// baseline (speedup 1.0000x reference)
#include <cuda_runtime.h>
#include <cstdint>
#include <math_constants.h>

// Problem constants: B=2, N=131072, M=512, G=20
#define BB 2
#define NN 131072
#define MM 512
#define GG 20
#define VV 8000
#define VOXINV 2.0f

#define BPB 128                 // blocks per batch
#define NBLK (BB * BPB)         // 256 blocks
#define NTHR 256                // 1 float4-group (4 points) per thread
#define MASKW 250               // VV bits / 32

// Device scratch (allocations forbidden in kernel_launch)
__device__ float        g_pmin[NBLK * 3];     // per-block partial mins
__device__ float        g_acc[BB * VV * 10];  // cnt, sx,sy,sz, xx,xy,xz,yy,yz,zz
__device__ unsigned int g_done;               // K2 block-completion counter

__device__ __forceinline__ int voxel_of(float px, float py, float pz,
                                        float n0, float n1, float n2) {
    int vx = (int)floorf((px - n0) * VOXINV);
    int vy = (int)floorf((py - n1) * VOXINV);
    int vz = (int)floorf((pz - n2) * VOXINV);
    vx = min(max(vx, 0), GG - 1);
    vy = min(max(vy, 0), GG - 1);
    vz = min(max(vz, 0), GG - 1);
    return (vx * GG + vy) * GG + vz;
}

// ============================================================================
// K1: zero accumulators/counter + per-block coordinate min (float4 loads)
// ============================================================================
__global__ void __launch_bounds__(NTHR)
k1_min(const float* __restrict__ x) {
    const int bid = blockIdx.x, tid = threadIdx.x;
    const int b = bid >> 7, br = bid & (BPB - 1);
    const int lane = tid & 31, w = tid >> 5;
    __shared__ float s_red[8 * 3];

    // zero g_acc (160k floats = 40960 uint4 -> 160 per block) + done counter
    {
        uint4* a4 = (uint4*)g_acc;
        if (tid < 160) a4[bid * 160 + tid] = make_uint4(0u, 0u, 0u, 0u);
        if (bid == 0 && tid == 0) g_done = 0u;
    }

    // one group of 4 points per thread: 3 independent float4 loads
    const float4* xb = (const float4*)(x + (size_t)b * NN * 3);
    int g = br * NTHR + tid;
    float4 f0 = __ldg(xb + (size_t)g * 3 + 0);
    float4 f1 = __ldg(xb + (size_t)g * 3 + 1);
    float4 f2 = __ldg(xb + (size_t)g * 3 + 2);
    float m0 = fminf(fminf(f0.x, f0.w), fminf(f1.z, f2.y));
    float m1 = fminf(fminf(f0.y, f1.x), fminf(f1.w, f2.z));
    float m2 = fminf(fminf(f0.z, f1.y), fminf(f2.x, f2.w));
#pragma unroll
    for (int o = 16; o > 0; o >>= 1) {
        m0 = fminf(m0, __shfl_xor_sync(0xFFFFFFFFu, m0, o));
        m1 = fminf(m1, __shfl_xor_sync(0xFFFFFFFFu, m1, o));
        m2 = fminf(m2, __shfl_xor_sync(0xFFFFFFFFu, m2, o));
    }
    if (lane == 0) { s_red[w*3+0] = m0; s_red[w*3+1] = m1; s_red[w*3+2] = m2; }
    __syncthreads();
    if (tid == 0) {
        float r0 = s_red[0], r1 = s_red[1], r2 = s_red[2];
#pragma unroll
        for (int k = 1; k < 8; k++) {
            r0 = fminf(r0, s_red[k*3+0]);
            r1 = fminf(r1, s_red[k*3+1]);
            r2 = fminf(r2, s_red[k*3+2]);
        }
        g_pmin[bid*3+0] = r0; g_pmin[bid*3+1] = r1; g_pmin[bid*3+2] = r2;
    }
}

// ============================================================================
// K2: smem mark + masked accumulation + last-block output epilogue.
// ============================================================================
__global__ void __launch_bounds__(NTHR)
k2_accum(const float* __restrict__ x, const int* __restrict__ sidx,
         float* __restrict__ out) {
    const int bid = blockIdx.x, tid = threadIdx.x;
    const int b = bid >> 7, br = bid & (BPB - 1);
    const int lane = tid & 31, w = tid >> 5;
    __shared__ float s_min[3];
    __shared__ unsigned int s_mask[MASKW];
    __shared__ unsigned int s_last;

    if (tid < MASKW) s_mask[tid] = 0u;
    // reduce this batch's 128 partial mins (warps 0..2, one component each)
    if (w < 3) {
        float m = CUDART_INF_F;
#pragma unroll
        for (int j = 0; j < BPB; j += 32)
            m = fminf(m, g_pmin[(b * BPB + j + lane) * 3 + w]);
#pragma unroll
        for (int o = 16; o > 0; o >>= 1)
            m = fminf(m, __shfl_xor_sync(0xFFFFFFFFu, m, o));
        if (lane == 0) s_min[w] = m;
    }
    __syncthreads();
    const float n0 = s_min[0], n1 = s_min[1], n2 = s_min[2];

    // Issue this thread's point-group loads EARLY (independent of mark work)
    const float4* xb = (const float4*)(x + (size_t)b * NN * 3);
    int g = br * NTHR + tid;
    float4 f0 = __ldg(xb + (size_t)g * 3 + 0);
    float4 f1 = __ldg(xb + (size_t)g * 3 + 1);
    float4 f2 = __ldg(xb + (size_t)g * 3 + 2);

    // Mark: 512 sampled points, 2 per thread (x gathers hit L2 after K1)
#pragma unroll
    for (int j = tid; j < MM; j += NTHR) {
        int i = __ldg(sidx + b * MM + j);
        const float* p = x + ((size_t)b * NN + i) * 3;
        int v = voxel_of(__ldg(p), __ldg(p + 1), __ldg(p + 2), n0, n1, n2);
        atomicOr(&s_mask[v >> 5], 1u << (v & 31));
    }
    __syncthreads();

    // Accumulate the 4 points of this thread's group
    float px[4] = {f0.x, f0.w, f1.z, f2.y};
    float py[4] = {f0.y, f1.x, f1.w, f2.z};
    float pz[4] = {f0.z, f1.y, f2.x, f2.w};
#pragma unroll
    for (int k = 0; k < 4; k++) {
        int v = voxel_of(px[k], py[k], pz[k], n0, n1, n2);
        if (s_mask[v >> 5] & (1u << (v & 31))) {
            float* a = &g_acc[(size_t)(b * VV + v) * 10];
            atomicAdd(a + 0, 1.0f);
            atomicAdd(a + 1, px[k]);
            atomicAdd(a + 2, py[k]);
            atomicAdd(a + 3, pz[k]);
            atomicAdd(a + 4, px[k] * px[k]);
            atomicAdd(a + 5, px[k] * py[k]);
            atomicAdd(a + 6, px[k] * pz[k]);
            atomicAdd(a + 7, py[k] * py[k]);
            atomicAdd(a + 8, py[k] * pz[k]);
            atomicAdd(a + 9, pz[k] * pz[k]);
        }
    }

    // ---- Completion handshake: last-arriving block runs the epilogue ----
    __syncthreads();                 // all atomics of this block issued
    if (tid == 0) {
        __threadfence();             // publish atomics before counting
        s_last = (atomicAdd(&g_done, 1u) == NBLK - 1) ? 1u : 0u;
    }
    __syncthreads();
    if (!s_last) return;

    // ===== Epilogue (one block): gather + finalize (B, M, 12) =====
    __shared__ float s_minall[6];    // [batch*3 + comp]
    if (w < 6) {                     // 6 warps: (batch, component) pairs
        int rb = w / 3, c = w % 3;
        float m = CUDART_INF_F;
#pragma unroll
        for (int j = 0; j < BPB; j += 32)
            m = fminf(m, g_pmin[(rb * BPB + j + lane) * 3 + c]);
#pragma unroll
        for (int o = 16; o > 0; o >>= 1)
            m = fminf(m, __shfl_xor_sync(0xFFFFFFFFu, m, o));
        if (lane == 0) s_minall[w] = m;
    }
    __syncthreads();

#pragma unroll
    for (int r = 0; r < 4; r++) {
        int t = r * NTHR + tid;      // 0..1023 = b*MM + j
        int eb = t >> 9;             // / MM
        int i = __ldg(sidx + t);
        const float* p = x + ((size_t)eb * NN + i) * 3;
        int v = voxel_of(__ldg(p), __ldg(p + 1), __ldg(p + 2),
                         s_minall[eb*3+0], s_minall[eb*3+1], s_minall[eb*3+2]);
        const float* a = &g_acc[(size_t)(eb * VV + v) * 10];

        float c0 = __ldcg(a + 0);
        float s1 = __ldcg(a + 1), s2 = __ldcg(a + 2), s3 = __ldcg(a + 3);
        float q4 = __ldcg(a + 4), q5 = __ldcg(a + 5), q6 = __ldcg(a + 6);
        float q7 = __ldcg(a + 7), q8 = __ldcg(a + 8), q9 = __ldcg(a + 9);

        float inv = 1.0f / fmaxf(c0, 1.0f);
        float mx = s1 * inv, my = s2 * inv, mz = s3 * inv;
        float cxx = q4 * inv - mx * mx;
        float cxy = q5 * inv - mx * my;
        float cxz = q6 * inv - mx * mz;
        float cyy = q7 * inv - my * my;
        float cyz = q8 * inv - my * mz;
        float czz = q9 * inv - mz * mz;

        float* o = out + (size_t)t * 12;
        o[0] = mx;  o[1] = my;  o[2] = mz;
        o[3] = cxx; o[4] = cxy; o[5] = cxz;
        o[6] = cxy; o[7] = cyy; o[8] = cyz;
        o[9] = cxz; o[10] = cyz; o[11] = czz;
    }
}

// ---------------------------------------------------------------------------
extern "C" void kernel_launch(void* const* d_in, const int* in_sizes, int n_in,
                              void* d_out, int out_size) {
    const float* x    = (const float*)d_in[0];   // (B, N, 3) f32
    const int*   sidx = (const int*)d_in[1];     // (B, M) i32
    float*       out  = (float*)d_out;           // (B, M, 12) f32

    k1_min<<<NBLK, NTHR>>>(x);
    k2_accum<<<NBLK, NTHR>>>(x, sidx, out);
}

// round 5
// speedup vs baseline: 1.8175x; 1.8175x over previous
#include <cuda_runtime.h>
#include <cstdint>
#include <math_constants.h>

// Problem constants: B=2, N=131072, M=512, G=20
#define BB 2
#define NN 131072
#define MM 512
#define GG 20
#define VV 8000
#define VOXINV 2.0f

#define NBLK 148                // one wave on 148+ SMs
#define BPB  74                 // blocks per batch
#define NTHR 256
#define GROUPS 32768            // NN/4 float4-groups per batch
#define MASKW 250               // VV bits / 32
#define ACCW  40000             // BB*VV*10 floats / 4 = uint4 words

// Device scratch (allocations forbidden). g_minc seeded +inf by static init,
// re-armed by k3 every launch (graph nodes serialize -> deterministic).
__device__ unsigned int g_minc[BB * 3] = {
    0x7F800000u, 0x7F800000u, 0x7F800000u,
    0x7F800000u, 0x7F800000u, 0x7F800000u};
__device__ float4 g_spts[BB * MM];      // compacted sampled points (.w unused)
__device__ float  g_acc[BB * VV * 10];  // cnt, sx,sy,sz, xx,xy,xz,yy,yz,zz

__device__ __forceinline__ int voxel_of(float px, float py, float pz,
                                        float n0, float n1, float n2) {
    int vx = (int)floorf((px - n0) * VOXINV);
    int vy = (int)floorf((py - n1) * VOXINV);
    int vz = (int)floorf((pz - n2) * VOXINV);
    vx = min(max(vx, 0), GG - 1);
    vy = min(max(vy, 0), GG - 1);
    vz = min(max(vz, 0), GG - 1);
    return (vx * GG + vy) * GG + vz;
}

// ============================================================================
// K1: zero g_acc + global min (atomicMin on uint bits) + compact sampled pts.
// ============================================================================
__global__ void __launch_bounds__(NTHR)
k1_min(const float* __restrict__ x, const int* __restrict__ sidx) {
    const int bid = blockIdx.x, tid = threadIdx.x;
    const int b = (bid < BPB) ? 0 : 1, br = bid - b * BPB;
    const int lane = tid & 31, w = tid >> 5;
    const int t = bid * NTHR + tid;
    __shared__ float s_red[8 * 3];

    // zero g_acc (grid-stride over 40000 uint4)
    {
        uint4* a4 = (uint4*)g_acc;
        for (int j = t; j < ACCW; j += NBLK * NTHR)
            a4[j] = make_uint4(0u, 0u, 0u, 0u);
    }

    // compact sampled points: first 1024 threads, one point each
    if (t < BB * MM) {
        int sb = t >> 9;
        int i = __ldg(sidx + t);
        const float* p = x + ((size_t)sb * NN + i) * 3;
        g_spts[t] = make_float4(__ldg(p), __ldg(p + 1), __ldg(p + 2), 0.0f);
    }

    // coordinate min over this batch's groups (1-2 float4-groups per thread)
    const float4* xb = (const float4*)(x + (size_t)b * NN * 3);
    float m0 = CUDART_INF_F, m1 = CUDART_INF_F, m2 = CUDART_INF_F;
    for (int g = br * NTHR + tid; g < GROUPS; g += BPB * NTHR) {
        float4 f0 = __ldg(xb + (size_t)g * 3 + 0);
        float4 f1 = __ldg(xb + (size_t)g * 3 + 1);
        float4 f2 = __ldg(xb + (size_t)g * 3 + 2);
        m0 = fminf(m0, fminf(fminf(f0.x, f0.w), fminf(f1.z, f2.y)));
        m1 = fminf(m1, fminf(fminf(f0.y, f1.x), fminf(f1.w, f2.z)));
        m2 = fminf(m2, fminf(fminf(f0.z, f1.y), fminf(f2.x, f2.w)));
    }
#pragma unroll
    for (int o = 16; o > 0; o >>= 1) {
        m0 = fminf(m0, __shfl_xor_sync(0xFFFFFFFFu, m0, o));
        m1 = fminf(m1, __shfl_xor_sync(0xFFFFFFFFu, m1, o));
        m2 = fminf(m2, __shfl_xor_sync(0xFFFFFFFFu, m2, o));
    }
    if (lane == 0) { s_red[w*3+0] = m0; s_red[w*3+1] = m1; s_red[w*3+2] = m2; }
    __syncthreads();
    if (tid == 0) {
        float r0 = s_red[0], r1 = s_red[1], r2 = s_red[2];
#pragma unroll
        for (int k = 1; k < 8; k++) {
            r0 = fminf(r0, s_red[k*3+0]);
            r1 = fminf(r1, s_red[k*3+1]);
            r2 = fminf(r2, s_red[k*3+2]);
        }
        // positive floats: uint bit order == float order
        atomicMin(&g_minc[b*3+0], __float_as_uint(r0));
        atomicMin(&g_minc[b*3+1], __float_as_uint(r1));
        atomicMin(&g_minc[b*3+2], __float_as_uint(r2));
    }
}

// ============================================================================
// K2: per-block smem mark from dense sampled buffer + masked accumulation.
// ============================================================================
__global__ void __launch_bounds__(NTHR)
k2_accum(const float* __restrict__ x) {
    const int bid = blockIdx.x, tid = threadIdx.x;
    const int b = (bid < BPB) ? 0 : 1, br = bid - b * BPB;
    __shared__ unsigned int s_mask[MASKW];

    if (tid < MASKW) s_mask[tid] = 0u;
    const float n0 = __uint_as_float(g_minc[b*3+0]);
    const float n1 = __uint_as_float(g_minc[b*3+1]);
    const float n2 = __uint_as_float(g_minc[b*3+2]);
    __syncthreads();

    // Mark this batch's 512 sampled voxels from the dense buffer (2 iters)
#pragma unroll
    for (int j = tid; j < MM; j += NTHR) {
        float4 p = g_spts[b * MM + j];
        int v = voxel_of(p.x, p.y, p.z, n0, n1, n2);
        atomicOr(&s_mask[v >> 5], 1u << (v & 31));
    }
    __syncthreads();

    // Masked accumulation over this batch's point groups (1-2 groups/thread)
    const float4* xb = (const float4*)(x + (size_t)b * NN * 3);
    for (int g = br * NTHR + tid; g < GROUPS; g += BPB * NTHR) {
        float4 f0 = __ldg(xb + (size_t)g * 3 + 0);
        float4 f1 = __ldg(xb + (size_t)g * 3 + 1);
        float4 f2 = __ldg(xb + (size_t)g * 3 + 2);
        float px[4] = {f0.x, f0.w, f1.z, f2.y};
        float py[4] = {f0.y, f1.x, f1.w, f2.z};
        float pz[4] = {f0.z, f1.y, f2.x, f2.w};
#pragma unroll
        for (int k = 0; k < 4; k++) {
            int v = voxel_of(px[k], py[k], pz[k], n0, n1, n2);
            if (s_mask[v >> 5] & (1u << (v & 31))) {
                float* a = &g_acc[(size_t)(b * VV + v) * 10];
                atomicAdd(a + 0, 1.0f);
                atomicAdd(a + 1, px[k]);
                atomicAdd(a + 2, py[k]);
                atomicAdd(a + 3, pz[k]);
                atomicAdd(a + 4, px[k] * px[k]);
                atomicAdd(a + 5, px[k] * py[k]);
                atomicAdd(a + 6, px[k] * pz[k]);
                atomicAdd(a + 7, py[k] * py[k]);
                atomicAdd(a + 8, py[k] * pz[k]);
                atomicAdd(a + 9, pz[k] * pz[k]);
            }
        }
    }
}

// ============================================================================
// K3: gather + finalize output (B, M, 12); re-arm g_minc for next launch.
// grid = 4 x 256 (threads map 1:1 to the 1024 outputs)
// ============================================================================
__global__ void __launch_bounds__(NTHR)
k3_out(float* __restrict__ out) {
    const int t = blockIdx.x * NTHR + threadIdx.x;   // 0..1023
    const int b = t >> 9;
    const float n0 = __uint_as_float(g_minc[b*3+0]);
    const float n1 = __uint_as_float(g_minc[b*3+1]);
    const float n2 = __uint_as_float(g_minc[b*3+2]);

    float4 p = g_spts[t];
    int v = voxel_of(p.x, p.y, p.z, n0, n1, n2);
    const float* a = &g_acc[(size_t)(b * VV + v) * 10];

    float inv = 1.0f / fmaxf(a[0], 1.0f);
    float mx = a[1] * inv, my = a[2] * inv, mz = a[3] * inv;
    float cxx = a[4] * inv - mx * mx;
    float cxy = a[5] * inv - mx * my;
    float cxz = a[6] * inv - mx * mz;
    float cyy = a[7] * inv - my * my;
    float cyz = a[8] * inv - my * mz;
    float czz = a[9] * inv - mz * mz;

    float* o = out + (size_t)t * 12;
    o[0] = mx;  o[1] = my;  o[2] = mz;
    o[3] = cxx; o[4] = cxy; o[5] = cxz;
    o[6] = cxy; o[7] = cyy; o[8] = cyz;
    o[9] = cxz; o[10] = cyz; o[11] = czz;

    // re-arm min for the next replay (nodes serialize within the graph)
    if (t < BB * 3) g_minc[t] = 0x7F800000u;
}

// ---------------------------------------------------------------------------
extern "C" void kernel_launch(void* const* d_in, const int* in_sizes, int n_in,
                              void* d_out, int out_size) {
    const float* x    = (const float*)d_in[0];   // (B, N, 3) f32
    const int*   sidx = (const int*)d_in[1];     // (B, M) i32
    float*       out  = (float*)d_out;           // (B, M, 12) f32

    k1_min<<<NBLK, NTHR>>>(x, sidx);
    k2_accum<<<NBLK, NTHR>>>(x);
    k3_out<<<4, NTHR>>>(out);
}